// round 17
// baseline (speedup 1.0000x reference)
#include <cuda_runtime.h>
#include <cuda_fp16.h>
#include <cstdint>
#include <cstddef>

// Problem constants
#define B_   16
#define CIN  512
#define HW   4096
#define G_   8
#define EPSG 1e-5f
#define STILES 32           // HW / 128
#define NPAIR 10            // triangle pairs of 128-blocks

// mainloop geometry: CTA tile 128x128, k-stage 32, 4-deep cp.async ring
#define AS_LD 20
#define BS_LD 68
#define A_STG 10240
#define STG_U 18944
#define STG_S 20480
#define SMEM_MAIN (4*STG_S) // 81920 -> 2 CTAs/SM

// merged prep grid: [0,512) prepM tiles, [512,1024) prepA rows, [1024, 33792) prepX
#define NPM 512
#define NPA 512
#define NPX 32768

// ---------------- device scratch ----------------
__device__ __half g_A16[CIN*CIN];                // Wcomb fp16
__device__ __half g_M16[G_*CIN*CIN];             // Msym per group fp16 (4 MB)
__device__ __half g_S[(size_t)B_*NPAIR*128*128]; // Gram tiles fp16 (5.2 MB)
__device__ __half g_x16[(size_t)B_*CIN*HW];      // x fp16 (67 MB)
__device__ __half g_u[(size_t)B_*CIN*HW];        // u fp16 (67 MB)
__device__ float  g_attp[B_*G_*NPAIR];
__device__ float  g_sump[B_*G_*STILES];
__device__ float  g_sumsqp[B_*G_*STILES];

// ---------------- PTX helpers ----------------
__device__ __forceinline__ uint32_t smem_u32(const void* p) {
    uint32_t a;
    asm("{ .reg .u64 t; cvta.to.shared.u64 t, %1; cvt.u32.u64 %0, t; }" : "=r"(a) : "l"(p));
    return a;
}
__device__ __forceinline__ void cpasync16(uint32_t dst, const void* src) {
    asm volatile("cp.async.cg.shared.global [%0], [%1], 16;" :: "r"(dst), "l"(src) : "memory");
}
#define CP_COMMIT()  asm volatile("cp.async.commit_group;" ::: "memory")
#define CP_WAIT(n)   asm volatile("cp.async.wait_group %0;" :: "n"(n) : "memory")

__device__ __forceinline__ void ldsm4(unsigned* r, uint32_t a) {
    asm volatile("ldmatrix.sync.aligned.m8n8.x4.shared.b16 {%0,%1,%2,%3}, [%4];"
        : "=r"(r[0]), "=r"(r[1]), "=r"(r[2]), "=r"(r[3]) : "r"(a));
}
__device__ __forceinline__ void ldsm4t(unsigned* r, uint32_t a) {
    asm volatile("ldmatrix.sync.aligned.m8n8.x4.trans.shared.b16 {%0,%1,%2,%3}, [%4];"
        : "=r"(r[0]), "=r"(r[1]), "=r"(r[2]), "=r"(r[3]) : "r"(a));
}
__device__ __forceinline__ void mma16(float* c, const unsigned* a, const unsigned* b) {
    asm volatile(
        "mma.sync.aligned.m16n8k16.row.col.f32.f16.f16.f32 "
        "{%0,%1,%2,%3}, {%4,%5,%6,%7}, {%8,%9}, {%0,%1,%2,%3};\n"
        : "+f"(c[0]), "+f"(c[1]), "+f"(c[2]), "+f"(c[3])
        : "r"(a[0]), "r"(a[1]), "r"(a[2]), "r"(a[3]), "r"(b[0]), "r"(b[1]));
}
__device__ __forceinline__ float wred(float v) {
#pragma unroll
    for (int o = 16; o; o >>= 1) v += __shfl_down_sync(0xffffffffu, v, o);
    return v;
}

// ---------------- K1: merged prep (prepM | prepA | prepX), one launch ----------------
__global__ void __launch_bounds__(256, 6)
k_prep(const float* __restrict__ x,  const float* __restrict__ Wt,
       const float* __restrict__ Wz, const float* __restrict__ Wp,
       const float* __restrict__ Wg) {
    __shared__ float sA[32*64];      // 8 KB
    __shared__ float sB[32*64];      // 8 KB
    __shared__ float wz[32];
    const int cta = blockIdx.x;
    const int tid = threadIdx.x;

    if (cta < NPM) {
        // ----- prepM: 64x64 tile of Msym[g] = 0.5(Wp_g^T Wg_g + Wg_g^T Wp_g) -----
        const int g  = cta >> 6;
        const int ib = (cta >> 3) & 7;
        const int jb = cta & 7;
        const int lrow = tid >> 4, lc4 = (tid & 15)*4;   // each thread: 2 rows per array
        const int i0 = (tid >> 4) * 4, j0 = (tid & 15) * 4;
        float m[4][4];
#pragma unroll
        for (int ii = 0; ii < 4; ii++)
#pragma unroll
            for (int jj = 0; jj < 4; jj++) m[ii][jj] = 0.f;

#pragma unroll
        for (int pass = 0; pass < 2; pass++) {
            const float* srcA = (pass == 0) ? Wp : Wg;   // rows for i-block
            const float* srcB = (pass == 0) ? Wg : Wp;   // rows for j-block
            __syncthreads();
#pragma unroll
            for (int h = 0; h < 2; h++) {
                int row = lrow + h*16;
                *(float4*)&sA[row*64 + lc4] =
                    *(const float4*)&srcA[(size_t)(32*g + row)*CIN + ib*64 + lc4];
                *(float4*)&sB[row*64 + lc4] =
                    *(const float4*)&srcB[(size_t)(32*g + row)*CIN + jb*64 + lc4];
            }
            __syncthreads();
            for (int c = 0; c < 32; c++) {
                float a4[4], b4[4];
#pragma unroll
                for (int q = 0; q < 4; q++) {
                    a4[q] = sA[c*64 + i0 + q];
                    b4[q] = sB[c*64 + j0 + q];
                }
#pragma unroll
                for (int ii = 0; ii < 4; ii++)
#pragma unroll
                    for (int jj = 0; jj < 4; jj++)
                        m[ii][jj] += a4[ii]*b4[jj];
            }
        }
#pragma unroll
        for (int ii = 0; ii < 4; ii++)
#pragma unroll
            for (int jj = 0; jj < 4; jj += 2) {
                __half2 h = __floats2half2_rn(0.5f*m[ii][jj], 0.5f*m[ii][jj+1]);
                *(__half2*)&g_M16[((size_t)g*CIN + ib*64 + i0 + ii)*CIN + jb*64 + j0 + jj] = h;
            }
    } else if (cta < NPM + NPA) {
        // ----- prepA: one Wcomb row -----
        const int r = cta - NPM;
        const int g = r >> 6, o = r & 63;
        if (tid < 32) wz[tid] = Wz[(size_t)(g*64 + o)*32 + tid];
        __syncthreads();
#pragma unroll
        for (int q = 0; q < 2; q++) {
            int i = tid + q*256;
            float a = 0.f;
#pragma unroll 8
            for (int c = 0; c < 32; c++)
                a += wz[c] * Wt[(size_t)(g*32 + c)*CIN + i];
            g_A16[(size_t)r*CIN + i] = __float2half(a);
        }
    } else {
        // ----- prepX: 256 float4 -> fp16 -----
        size_t i = (size_t)(cta - NPM - NPA) * 256 + tid;
        float4 v = __ldcs(&((const float4*)x)[i]);
        __half2* d = (__half2*)g_x16;
        d[2*i]     = __floats2half2_rn(v.x, v.y);
        d[2*i + 1] = __floats2half2_rn(v.z, v.w);
    }
}

// ---------------- K2: unified mainloop (S tiles first, then u tiles) — round-11 proven ----------------
__global__ void __launch_bounds__(256, 2)
k_main() {
    extern __shared__ char smem[];
    const uint32_t sb = smem_u32(smem);
    __shared__ float rbuf[16];

    const int tid  = threadIdx.x;
    const int lane = tid & 31, warp = tid >> 5;
    const int wm = warp >> 1, wn = warp & 1;
    const int cta = blockIdx.x;
    const int lr = lane >> 2, lc2 = (lane & 3)*2;

    if (cta < 160) {
        // ===== S-path: S = X[chi] @ X[chj]^T, K = 4096, store tile fp16 =====
        const int pr = cta % NPAIR;
        const int b  = cta / NPAIR;
        int ib = 0, rem = pr;
        while (rem > ib) { rem -= (ib + 1); ib++; }
        const int jb = rem;
        const int chi = ib*128, chj = jb*128;

        const int row = tid >> 1, ah = tid & 1;
        const __half* isrc = g_x16 + ((size_t)b*CIN + chi + row)*HW + ah*16;
        const __half* jsrc = g_x16 + ((size_t)b*CIN + chj + row)*HW + ah*16;
        const uint32_t idst = sb + row*80 + ah*32;
        const uint32_t jdst = idst + A_STG;

        auto issue = [&](int s) {
            if (s < 128) {
                const int st = (s & 3)*STG_S;
                cpasync16(idst + st,      isrc + s*32);
                cpasync16(idst + st + 16, isrc + s*32 + 8);
                cpasync16(jdst + st,      jsrc + s*32);
                cpasync16(jdst + st + 16, jsrc + s*32 + 8);
            }
            CP_COMMIT();
        };

        const int l15 = lane & 15, lk = (lane >> 4) * 16;

        float acc[2][8][4];
#pragma unroll
        for (int mt = 0; mt < 2; mt++)
#pragma unroll
            for (int nt = 0; nt < 8; nt++)
#pragma unroll
                for (int i = 0; i < 4; i++) acc[mt][nt][i] = 0.f;

        issue(0);
        issue(1);
        for (int s = 0; s < 128; s++) {
            issue(s + 2);
            CP_WAIT(2);
            __syncthreads();
            const uint32_t xi = sb + (s & 3)*STG_S;
            const uint32_t xj = xi + A_STG;
#pragma unroll
            for (int ks = 0; ks < 2; ks++) {
                unsigned af[2][4], bf[4][4];
#pragma unroll
                for (int mt = 0; mt < 2; mt++)
                    ldsm4(af[mt], xi + (wm*32 + mt*16 + l15)*80 + ks*32 + lk);
#pragma unroll
                for (int ng = 0; ng < 4; ng++)
                    ldsm4(bf[ng], xj + (wn*64 + ng*16 + l15)*80 + ks*32 + lk);
#pragma unroll
                for (int ng = 0; ng < 4; ng++) {
                    unsigned blo[2] = { bf[ng][0], bf[ng][2] };
                    unsigned bhi[2] = { bf[ng][1], bf[ng][3] };
#pragma unroll
                    for (int mt = 0; mt < 2; mt++) {
                        mma16(acc[mt][2*ng],     af[mt], blo);
                        mma16(acc[mt][2*ng + 1], af[mt], bhi);
                    }
                }
            }
        }
        CP_WAIT(0);
        __syncthreads();

        __half* sdst = g_S + ((size_t)(b*NPAIR + pr) << 14);
#pragma unroll
        for (int mt = 0; mt < 2; mt++)
#pragma unroll
            for (int nt = 0; nt < 8; nt++)
#pragma unroll
                for (int i2 = 0; i2 < 2; i2++) {
                    int r = wm*32 + mt*16 + lr + i2*8;
                    int c = wn*64 + nt*8 + lc2;
                    *(__half2*)&sdst[r*128 + c] =
                        __floats2half2_rn(acc[mt][nt][i2*2], acc[mt][nt][i2*2 + 1]);
                }
    } else {
        // ===== u-path: C = Wcomb[yy*128..] @ X[b][:, stile*128..] =====
        const int cta2 = cta - 160;
        const int stile = cta2 & 31, yy = (cta2 >> 5) & 3, b = cta2 >> 7;
        const int scol0 = stile * 128;

        const int arow = tid >> 1, ah = tid & 1;
        const __half* asrc = g_A16 + ((size_t)yy*128 + arow)*CIN + ah*16;
        const uint32_t adst = sb + arow*80 + ah*32;
        const int bk = (tid >> 4), bn16 = tid & 15;
        const __half* bsrc0 = g_x16 + ((size_t)b*CIN + bk)*HW + scol0 + bn16*8;
        const uint32_t bdst = sb + A_STG + bk*272 + bn16*16;

        auto issue = [&](int s) {
            if (s < 16) {
                const int st = (s & 3)*STG_U;
                cpasync16(adst + st,          asrc + s*32);
                cpasync16(adst + st + 16,     asrc + s*32 + 8);
                cpasync16(bdst + st,          bsrc0 + (size_t)s*32*HW);
                cpasync16(bdst + st + 16*272, bsrc0 + (size_t)(s*32 + 16)*HW);
            }
            CP_COMMIT();
        };

        const int a_row = wm*32 + (lane & 15);
        const int a_kw  = (lane >> 4) * 4;
        const int b_k   = lane & 15;
        const int b_w   = (lane >> 4) * 4;

        float acc[2][8][4];
#pragma unroll
        for (int mt = 0; mt < 2; mt++)
#pragma unroll
            for (int nt = 0; nt < 8; nt++)
#pragma unroll
                for (int i = 0; i < 4; i++) acc[mt][nt][i] = 0.f;

        issue(0);
        issue(1);
        for (int s = 0; s < 16; s++) {
            issue(s + 2);
            CP_WAIT(2);
            __syncthreads();
            const uint32_t abuf = sb + (s & 3)*STG_U;
            const uint32_t bbuf = abuf + A_STG;
#pragma unroll
            for (int ks = 0; ks < 2; ks++) {
                unsigned af[2][4], bf[4][4];
#pragma unroll
                for (int mt = 0; mt < 2; mt++)
                    ldsm4(af[mt], abuf + ((a_row + mt*16)*AS_LD + ks*8 + a_kw)*4);
#pragma unroll
                for (int ng = 0; ng < 4; ng++)
                    ldsm4t(bf[ng], bbuf + ((ks*16 + b_k)*BS_LD + wn*32 + ng*8 + b_w)*4);
#pragma unroll
                for (int mt = 0; mt < 2; mt++)
#pragma unroll
                    for (int ng = 0; ng < 4; ng++) {
                        mma16(acc[mt][2*ng],     af[mt], &bf[ng][0]);
                        mma16(acc[mt][2*ng + 1], af[mt], &bf[ng][2]);
                    }
            }
        }
        CP_WAIT(0);
        __syncthreads();

        float s1 = 0.f, s2 = 0.f;
        const size_t ub = ((size_t)b*CIN + yy*128 + wm*32)*HW + scol0 + wn*64;
#pragma unroll
        for (int mt = 0; mt < 2; mt++)
#pragma unroll
            for (int nt = 0; nt < 8; nt++)
#pragma unroll
                for (int i2 = 0; i2 < 2; i2++) {
                    float v0 = acc[mt][nt][i2*2], v1 = acc[mt][nt][i2*2 + 1];
                    int r = mt*16 + lr + i2*8;
                    int c = nt*8 + lc2;
                    *(__half2*)&g_u[ub + (size_t)r*HW + c] = __floats2half2_rn(v0, v1);
                    s1 += v0 + v1;
                    s2 += v0*v0 + v1*v1;
                }
        s1 = wred(s1); s2 = wred(s2);
        if (lane == 0) { rbuf[warp] = s1; rbuf[8 + warp] = s2; }
        __syncthreads();
        if (tid < 2) {
            int g = yy*2 + tid;
            float ss = rbuf[tid*4] + rbuf[tid*4+1] + rbuf[tid*4+2] + rbuf[tid*4+3];
            float qq = rbuf[8+tid*4] + rbuf[8+tid*4+1] + rbuf[8+tid*4+2] + rbuf[8+tid*4+3];
            g_sump[(b*G_ + g)*STILES + stile]   = ss;
            g_sumsqp[(b*G_ + g)*STILES + stile] = qq;
        }
    }
}

// ---------------- K3: att partials = fac * <S_tile, M_g tile> (round-11 proven) ----------------
__global__ void k_att() {
    __shared__ float rb[64];
    const int cta = blockIdx.x;
    const int pr = cta % NPAIR, b = cta / NPAIR;
    int ib = 0, rem = pr;
    while (rem > ib) { rem -= (ib + 1); ib++; }
    const int jb = rem;
    const float fac = (ib == jb) ? 1.f : 2.f;

    const int tid = threadIdx.x, lane = tid & 31, warp = tid >> 5;
    const int r = tid >> 1, c0 = (tid & 1)*64;

    const __half* sp = g_S + ((size_t)(b*NPAIR + pr) << 14) + r*128 + c0;
    float sv[64];
#pragma unroll
    for (int q = 0; q < 8; q++) {
        uint4 v = *(const uint4*)(sp + q*8);
        const __half2* h = (const __half2*)&v;
#pragma unroll
        for (int p = 0; p < 4; p++) {
            float2 f = __half22float2(h[p]);
            sv[q*8 + p*2]     = f.x;
            sv[q*8 + p*2 + 1] = f.y;
        }
    }

    for (int g = 0; g < G_; g++) {
        const __half* mp = g_M16 + ((size_t)g*CIN + ib*128 + r)*CIN + jb*128 + c0;
        float a = 0.f;
#pragma unroll
        for (int q = 0; q < 8; q++) {
            uint4 mv = *(const uint4*)(mp + q*8);
            const __half2* mh = (const __half2*)&mv;
#pragma unroll
            for (int p = 0; p < 4; p++) {
                float2 mf = __half22float2(mh[p]);
                a += sv[q*8 + p*2]*mf.x + sv[q*8 + p*2 + 1]*mf.y;
            }
        }
        a = wred(a);
        if (lane == 0) rb[g*8 + warp] = a;
    }
    __syncthreads();
    if (tid < G_) {
        float a = 0.f;
#pragma unroll
        for (int w2 = 0; w2 < 8; w2++) a += rb[tid*8 + w2];
        g_attp[(b*G_ + tid)*NPAIR + pr] = a * fac;
    }
}

// ---------------- K4: fused stats + out = scale*u + bias + x ----------------
__global__ void k_final(const float* __restrict__ gamma, const float* __restrict__ beta,
                        float* __restrict__ out) {
    const int cta = blockIdx.x, tid = threadIdx.x;
    const size_t e0 = (size_t)cta << 10;
    const int b = (int)(e0 >> 21);
    const int c = (int)((e0 >> 12) & 511);
    const int g = c >> 6;

    __shared__ float s_sc, s_bi;
    if (tid < 32) {
        float sm = g_sump[(b*G_ + g)*STILES + tid];
        float sq = g_sumsqp[(b*G_ + g)*STILES + tid];
        float at = (tid < NPAIR) ? g_attp[(b*G_ + g)*NPAIR + tid] : 0.f;
        sm = wred(sm); sq = wred(sq); at = wred(at);
        if (tid == 0) {
            const float n = 64.0f * 4096.0f;
            float mu  = sm / n;
            float var = fmaxf(sq / n - mu*mu, 0.f);
            float rstd = rsqrtf(at*at*var + EPSG);
            float S = at * rstd;
            float gm = gamma[c];
            s_sc = S * gm;
            s_bi = beta[c] - S * mu * gm;
        }
    }
    __syncthreads();
    const float sc = s_sc, bi = s_bi;

    const size_t i = (size_t)cta * 256 + tid;
    const __half2* up = (const __half2*)g_u;
    const __half2* xp = (const __half2*)g_x16;
    float2 u0 = __half22float2(__ldcs(&up[2*i]));
    float2 u1 = __half22float2(__ldcs(&up[2*i + 1]));
    float2 x0 = __half22float2(__ldcs(&xp[2*i]));
    float2 x1 = __half22float2(__ldcs(&xp[2*i + 1]));
    float4 o;
    o.x = fmaf(sc, u0.x, bi + x0.x);
    o.y = fmaf(sc, u0.y, bi + x0.y);
    o.z = fmaf(sc, u1.x, bi + x1.x);
    o.w = fmaf(sc, u1.y, bi + x1.y);
    __stcs(&((float4*)out)[i], o);
}

// ---------------- launch ----------------
extern "C" void kernel_launch(void* const* d_in, const int* in_sizes, int n_in,
                              void* d_out, int out_size) {
    const float* x     = (const float*)d_in[0];
    const float* Wt    = (const float*)d_in[1];
    const float* Wp    = (const float*)d_in[2];
    const float* Wg    = (const float*)d_in[3];
    const float* Wz    = (const float*)d_in[4];
    const float* gamma = (const float*)d_in[5];
    const float* beta  = (const float*)d_in[6];
    float* out = (float*)d_out;

    cudaFuncSetAttribute(k_main, cudaFuncAttributeMaxDynamicSharedMemorySize, SMEM_MAIN);

    k_prep<<<NPM + NPA + NPX, 256>>>(x, Wt, Wz, Wp, Wg);
    k_main<<<160 + 2048, 256, SMEM_MAIN>>>();
    k_att<<<160, 256>>>();
    k_final<<<32768, 256>>>(gamma, beta, out);
}